// round 6
// baseline (speedup 1.0000x reference)
#include <cuda_runtime.h>

// SGC: out = S^2 (X w) + b,  S = D^-1/2 (A+I) D^-1/2.
// Propagate ONE scalar per node; factor dis[c] out of the edge loop:
//   t[c]  = sum_edges z[r],  z = dis*y
//   y1    = dis*t1 + y0/deg
//   out   = dis*(t2 + dis*y1) + b

#define NN 100000
#define EE 600000
#define DD 128
#define TB 256
#define EPT 4                       // edges per thread (EE % 4 == 0)
#define EDGE_THREADS (EE / EPT)     // 150000
#define EDGE_BLOCKS ((EDGE_THREADS + TB - 1) / TB)   // 586
#define DOT_BLOCKS (NN / 4 * 32 / TB)                // 3125 (exact)

__device__ float g_deg[NN];
__device__ float g_dis[NN];
__device__ float g_y0[NN];
__device__ float g_z0[NN];      // dis * y0
__device__ float g_y1s[NN];     // y0 / deg
__device__ float g_z1[NN];      // dis * y1
__device__ float g_t1[NN];
__device__ float g_t2[NN];
__device__ int   g_is64;

// ---------------------------------------------------------------------------
__global__ void k_init(const void* __restrict__ ei) {
    int i = blockIdx.x * blockDim.x + threadIdx.x;
    if (i < NN) { g_deg[i] = 1.0f; g_t1[i] = 0.0f; g_t2[i] = 0.0f; }
    if (i == 0) {
        // sniff int64 vs int32 (int32 data seen as int64 => random high word)
        const long long* p = (const long long*)ei;
        int ok = 1;
        #pragma unroll
        for (int k = 0; k < 16; k++) {
            long long v = p[k];
            if (v < 0 || v >= (long long)NN) ok = 0;
        }
        g_is64 = ok;
    }
}

// Load 4 consecutive indices from half (0=row, 1=col) starting at edge 4*t.
__device__ __forceinline__ void load_idx4(const void* ei, int t, int half,
                                          int is64, int idx[4]) {
    if (is64) {
        const long long* p = (const long long*)ei + (size_t)half * EE;
        longlong2 a = ((const longlong2*)p)[2 * t];
        longlong2 b = ((const longlong2*)p)[2 * t + 1];
        idx[0] = (int)a.x; idx[1] = (int)a.y; idx[2] = (int)b.x; idx[3] = (int)b.y;
    } else {
        const int* p = (const int*)ei + (size_t)half * EE;
        int4 v = ((const int4*)p)[t];
        idx[0] = v.x; idx[1] = v.y; idx[2] = v.z; idx[3] = v.w;
    }
}

// ---------------------------------------------------------------------------
// Fused: edge blocks (first, short, L2-atomic bound) accumulate deg;
// dot blocks (DRAM-bound) compute y0.  Independent work overlaps.
__global__ void __launch_bounds__(TB) k_deg_dot(const void* __restrict__ ei,
                                                const float* __restrict__ x,
                                                const float* __restrict__ W) {
    if (blockIdx.x < EDGE_BLOCKS) {
        int t = blockIdx.x * TB + threadIdx.x;
        if (t >= EDGE_THREADS) return;
        int c[4];
        load_idx4(ei, t, 1, g_is64, c);
        #pragma unroll
        for (int j = 0; j < 4; j++) atomicAdd(&g_deg[c[j]], 1.0f);
        return;
    }
    // ---- dot part: 4 nodes per warp, MLP=4 ----
    int t = (blockIdx.x - EDGE_BLOCKS) * TB + threadIdx.x;
    int warp = t >> 5;
    int lane = t & 31;
    int base = warp * 4;
    if (base >= NN) return;
    float4 wv = __ldg(((const float4*)W) + lane);

    float4 xv[4];
    #pragma unroll
    for (int j = 0; j < 4; j++)
        xv[j] = __ldg(((const float4*)(x + (size_t)(base + j) * DD)) + lane);

    float s0 = xv[0].x * wv.x + xv[0].y * wv.y + xv[0].z * wv.z + xv[0].w * wv.w;
    float s1 = xv[1].x * wv.x + xv[1].y * wv.y + xv[1].z * wv.z + xv[1].w * wv.w;
    float s2 = xv[2].x * wv.x + xv[2].y * wv.y + xv[2].z * wv.z + xv[2].w * wv.w;
    float s3 = xv[3].x * wv.x + xv[3].y * wv.y + xv[3].z * wv.z + xv[3].w * wv.w;

    #pragma unroll
    for (int o = 16; o; o >>= 1) {
        s0 += __shfl_xor_sync(0xffffffffu, s0, o);
        s1 += __shfl_xor_sync(0xffffffffu, s1, o);
        s2 += __shfl_xor_sync(0xffffffffu, s2, o);
        s3 += __shfl_xor_sync(0xffffffffu, s3, o);
    }

    if (lane < 4) {
        float y0 = (lane == 0) ? s0 : (lane == 1) ? s1 : (lane == 2) ? s2 : s3;
        g_y0[base + lane] = y0;
    }
}

// Finalize per-node normalization after deg is complete.
__global__ void k_prep() {
    int i = blockIdx.x * blockDim.x + threadIdx.x;
    if (i >= NN) return;
    float deg = g_deg[i];
    float y0  = g_y0[i];
    float dis = rsqrtf(deg);
    g_dis[i] = dis;
    g_z0[i]  = dis * y0;
    g_y1s[i] = y0 / deg;
}

// Edge scatter, 4 edges/thread: t[c] += z[r].
template <int PASS>
__global__ void __launch_bounds__(TB) k_pass(const void* __restrict__ ei) {
    int t = blockIdx.x * blockDim.x + threadIdx.x;
    if (t >= EDGE_THREADS) return;
    int is64 = g_is64;
    int r[4], c[4];
    load_idx4(ei, t, 0, is64, r);
    load_idx4(ei, t, 1, is64, c);
    const float* src = (PASS == 1) ? g_z0 : g_z1;
    float*       dst = (PASS == 1) ? g_t1 : g_t2;
    float v0 = __ldg(&src[r[0]]);
    float v1 = __ldg(&src[r[1]]);
    float v2 = __ldg(&src[r[2]]);
    float v3 = __ldg(&src[r[3]]);
    atomicAdd(&dst[c[0]], v0);
    atomicAdd(&dst[c[1]], v1);
    atomicAdd(&dst[c[2]], v2);
    atomicAdd(&dst[c[3]], v3);
}

// z1 = dis * (dis*t1 + y0/deg)
__global__ void k_mid() {
    int i = blockIdx.x * blockDim.x + threadIdx.x;
    if (i >= NN) return;
    float dis = g_dis[i];
    g_z1[i] = dis * (dis * g_t1[i] + g_y1s[i]);
}

// out = dis*(t2 + z1) + b
__global__ void k_final(float* __restrict__ out, const float* __restrict__ b) {
    int i = blockIdx.x * blockDim.x + threadIdx.x;
    if (i >= NN) return;
    out[i] = g_dis[i] * (g_t2[i] + g_z1[i]) + b[0];
}

// ---------------------------------------------------------------------------
extern "C" void kernel_launch(void* const* d_in, const int* in_sizes, int n_in,
                              void* d_out, int out_size) {
    const float* x  = (const float*)d_in[0];
    const void*  ei = d_in[1];
    const float* W  = (const float*)d_in[2];
    const float* b  = (const float*)d_in[3];
    float* out = (float*)d_out;

    k_init   <<<(NN + TB - 1) / TB, TB>>>(ei);
    k_deg_dot<<<EDGE_BLOCKS + DOT_BLOCKS, TB>>>(ei, x, W);
    k_prep   <<<(NN + TB - 1) / TB, TB>>>();
    k_pass<1><<<EDGE_BLOCKS, TB>>>(ei);
    k_mid    <<<(NN + TB - 1) / TB, TB>>>();
    k_pass<2><<<EDGE_BLOCKS, TB>>>(ei);
    k_final  <<<(NN + TB - 1) / TB, TB>>>(out, b);
}

// round 7
// speedup vs baseline: 1.2489x; 1.2489x over previous
#include <cuda_runtime.h>

// SGC: out = S^2 (X w) + b,  S = D^-1/2 (A+I) D^-1/2.
// Propagate ONE scalar per node; factor dis[c] out of the edge loop:
//   t[c]  = sum_edges z[r],  z = dis*y
//   y1    = dis*t1 + y0/deg
//   out   = dis*(t2 + dis*y1) + b

#define NN 100000
#define EE 600000
#define DD 128
#define TB 256
#define EDGE_BLOCKS ((EE + TB - 1) / TB)   // 2344 (1 edge/thread)
#define DOT_BLOCKS  (NN / 4 * 32 / TB)     // 3125 (exact)

__device__ float g_deg[NN];
__device__ float g_dis[NN];
__device__ float g_y0[NN];
__device__ float g_z0[NN];      // dis * y0
__device__ float g_y1s[NN];     // y0 / deg
__device__ float g_z1[NN];      // dis * y1
__device__ float g_t1[NN];
__device__ float g_t2[NN];
__device__ int2  g_pairs[EE];   // packed (row, col) int32 — L2-resident
__device__ int   g_is64;

// ---------------------------------------------------------------------------
__global__ void k_init(const void* __restrict__ ei) {
    int i = blockIdx.x * blockDim.x + threadIdx.x;
    if (i < NN) { g_deg[i] = 1.0f; g_t1[i] = 0.0f; g_t2[i] = 0.0f; }
    if (i == 0) {
        // sniff int64 vs int32 (int32 data viewed as int64 => random high word;
        // 16 consecutive false positives has prob ~1e-80)
        const long long* p = (const long long*)ei;
        int ok = 1;
        #pragma unroll
        for (int k = 0; k < 16; k++) {
            long long v = p[k];
            if (v < 0 || v >= (long long)NN) ok = 0;
        }
        g_is64 = ok;
    }
}

__device__ __forceinline__ int load_idx(const void* ei, int e, int half, int is64) {
    if (is64) return (int)(((const long long*)ei)[(size_t)half * EE + e]);
    return ((const int*)ei)[half * EE + e];
}

// ---------------------------------------------------------------------------
// Fused kernel: edge blocks (first) do deg-count AND pack (r,c) into int2;
// dot blocks (DRAM-bound, dominant) compute y0.  The two are independent.
__global__ void __launch_bounds__(TB) k_deg_dot(const void* __restrict__ ei,
                                                const float* __restrict__ x,
                                                const float* __restrict__ W) {
    if (blockIdx.x < EDGE_BLOCKS) {
        int e = blockIdx.x * TB + threadIdx.x;
        if (e >= EE) return;
        int is64 = g_is64;
        int r = load_idx(ei, e, 0, is64);
        int c = load_idx(ei, e, 1, is64);
        g_pairs[e] = make_int2(r, c);
        atomicAdd(&g_deg[c], 1.0f);
        return;
    }
    // ---- dot part: 4 nodes per warp, MLP=4 ----
    int t = (blockIdx.x - EDGE_BLOCKS) * TB + threadIdx.x;
    int warp = t >> 5;
    int lane = t & 31;
    int base = warp * 4;
    if (base >= NN) return;
    float4 wv = __ldg(((const float4*)W) + lane);

    float4 xv[4];
    #pragma unroll
    for (int j = 0; j < 4; j++)
        xv[j] = __ldg(((const float4*)(x + (size_t)(base + j) * DD)) + lane);

    float s0 = xv[0].x * wv.x + xv[0].y * wv.y + xv[0].z * wv.z + xv[0].w * wv.w;
    float s1 = xv[1].x * wv.x + xv[1].y * wv.y + xv[1].z * wv.z + xv[1].w * wv.w;
    float s2 = xv[2].x * wv.x + xv[2].y * wv.y + xv[2].z * wv.z + xv[2].w * wv.w;
    float s3 = xv[3].x * wv.x + xv[3].y * wv.y + xv[3].z * wv.z + xv[3].w * wv.w;

    #pragma unroll
    for (int o = 16; o; o >>= 1) {
        s0 += __shfl_xor_sync(0xffffffffu, s0, o);
        s1 += __shfl_xor_sync(0xffffffffu, s1, o);
        s2 += __shfl_xor_sync(0xffffffffu, s2, o);
        s3 += __shfl_xor_sync(0xffffffffu, s3, o);
    }

    if (lane < 4) {
        float y0 = (lane == 0) ? s0 : (lane == 1) ? s1 : (lane == 2) ? s2 : s3;
        g_y0[base + lane] = y0;
    }
}

// Finalize per-node normalization after deg is complete.
__global__ void k_prep() {
    int i = blockIdx.x * blockDim.x + threadIdx.x;
    if (i >= NN) return;
    float deg = g_deg[i];
    float y0  = g_y0[i];
    float dis = rsqrtf(deg);
    g_dis[i] = dis;
    g_z0[i]  = dis * y0;
    g_y1s[i] = y0 / deg;
}

// Edge scatter, 1 edge/thread, 3 mem ops: LDG.64 pair -> gather -> RED.
template <int PASS>
__global__ void __launch_bounds__(TB) k_pass() {
    int e = blockIdx.x * blockDim.x + threadIdx.x;
    if (e >= EE) return;
    int2 p = g_pairs[e];
    if (PASS == 1) atomicAdd(&g_t1[p.y], __ldg(&g_z0[p.x]));
    else           atomicAdd(&g_t2[p.y], __ldg(&g_z1[p.x]));
}

// z1 = dis * (dis*t1 + y0/deg)
__global__ void k_mid() {
    int i = blockIdx.x * blockDim.x + threadIdx.x;
    if (i >= NN) return;
    float dis = g_dis[i];
    g_z1[i] = dis * (dis * g_t1[i] + g_y1s[i]);
}

// out = dis*(t2 + z1) + b
__global__ void k_final(float* __restrict__ out, const float* __restrict__ b) {
    int i = blockIdx.x * blockDim.x + threadIdx.x;
    if (i >= NN) return;
    out[i] = g_dis[i] * (g_t2[i] + g_z1[i]) + b[0];
}

// ---------------------------------------------------------------------------
extern "C" void kernel_launch(void* const* d_in, const int* in_sizes, int n_in,
                              void* d_out, int out_size) {
    const float* x  = (const float*)d_in[0];
    const void*  ei = d_in[1];
    const float* W  = (const float*)d_in[2];
    const float* b  = (const float*)d_in[3];
    float* out = (float*)d_out;

    k_init   <<<(NN + TB - 1) / TB, TB>>>(ei);
    k_deg_dot<<<EDGE_BLOCKS + DOT_BLOCKS, TB>>>(ei, x, W);
    k_prep   <<<(NN + TB - 1) / TB, TB>>>();
    k_pass<1><<<EDGE_BLOCKS, TB>>>();
    k_mid    <<<(NN + TB - 1) / TB, TB>>>();
    k_pass<2><<<EDGE_BLOCKS, TB>>>();
    k_final  <<<(NN + TB - 1) / TB, TB>>>(out, b);
}

// round 11
// speedup vs baseline: 1.3949x; 1.1169x over previous
#include <cuda_runtime.h>

// SGC: out = S^2 (X w) + b,  S = D^-1/2 (A+I) D^-1/2.
// Propagate ONE scalar per node; factor dis[c] out of the edge loop:
//   t[c]  = sum_edges z[r],  z = dis*y
//   y1    = dis*t1 + y0/deg
//   out   = dis*(t2 + dis*y1) + b
// No init kernel: degcnt/t1/t2 start zero (BSS) and are re-zeroed by k_final,
// so every kernel_launch call sees a clean state.

#define NN 100000
#define EE 600000
#define DD 128
#define TB 256
#define EDGE_BLOCKS ((EE + TB - 1) / TB)          // 2344 (1 edge/thread)
#define DOT_BLOCKS  ((NN / 8 * 32 + TB - 1) / TB) // 1563 (8 nodes/warp)

__device__ int   g_degcnt[NN];  // in-degree (without self loop); zero at rest
__device__ float g_dis[NN];
__device__ float g_y0[NN];
__device__ float g_z0[NN];      // dis * y0
__device__ float g_y1s[NN];     // y0 / deg
__device__ float g_z1[NN];      // dis * y1
__device__ float g_t1[NN];      // zero at rest
__device__ float g_t2[NN];      // zero at rest
__device__ int2  g_pairs[EE];   // packed (row, col) int32 — L2-resident

// ---------------------------------------------------------------------------
// Fused kernel.  Dot blocks FIRST (long, DRAM-bound); edge blocks after
// (cheap, L2-atomic bound) — independent work overlaps.
__global__ void __launch_bounds__(TB) k_deg_dot(const void* __restrict__ ei,
                                                const float* __restrict__ x,
                                                const float* __restrict__ W) {
    if (blockIdx.x >= DOT_BLOCKS) {
        // ---- edge part: sniff dtype locally, pack pair, count degree ----
        int e = (blockIdx.x - DOT_BLOCKS) * TB + threadIdx.x;
        if (e >= EE) return;
        // int32 data viewed as int64 puts a random node index in the high
        // word; 16 consecutive in-range int64s => genuinely int64 (~1e-80 fp).
        const long long* p64 = (const long long*)ei;
        int is64 = 1;
        #pragma unroll
        for (int k = 0; k < 16; k++) {
            long long v = p64[k];
            if (v < 0 || v >= (long long)NN) is64 = 0;
        }
        int r, c;
        if (is64) {
            r = (int)p64[e];
            c = (int)p64[EE + e];
        } else {
            const int* p32 = (const int*)ei;
            r = p32[e];
            c = p32[EE + e];
        }
        g_pairs[e] = make_int2(r, c);
        atomicAdd(&g_degcnt[c], 1);
        return;
    }
    // ---- dot part: 8 nodes per warp, 8 front-batched float4 loads (MLP=8) ----
    int t = blockIdx.x * TB + threadIdx.x;
    int warp = t >> 5;
    int lane = t & 31;
    int base = warp * 8;                 // NN % 8 == 0
    if (base >= NN) return;
    float4 wv = __ldg(((const float4*)W) + lane);

    float4 xv[8];
    #pragma unroll
    for (int j = 0; j < 8; j++)
        xv[j] = __ldg(((const float4*)(x + (size_t)(base + j) * DD)) + lane);

    float s0 = xv[0].x * wv.x + xv[0].y * wv.y + xv[0].z * wv.z + xv[0].w * wv.w;
    float s1 = xv[1].x * wv.x + xv[1].y * wv.y + xv[1].z * wv.z + xv[1].w * wv.w;
    float s2 = xv[2].x * wv.x + xv[2].y * wv.y + xv[2].z * wv.z + xv[2].w * wv.w;
    float s3 = xv[3].x * wv.x + xv[3].y * wv.y + xv[3].z * wv.z + xv[3].w * wv.w;
    float s4 = xv[4].x * wv.x + xv[4].y * wv.y + xv[4].z * wv.z + xv[4].w * wv.w;
    float s5 = xv[5].x * wv.x + xv[5].y * wv.y + xv[5].z * wv.z + xv[5].w * wv.w;
    float s6 = xv[6].x * wv.x + xv[6].y * wv.y + xv[6].z * wv.z + xv[6].w * wv.w;
    float s7 = xv[7].x * wv.x + xv[7].y * wv.y + xv[7].z * wv.z + xv[7].w * wv.w;

    #pragma unroll
    for (int o = 16; o; o >>= 1) {
        s0 += __shfl_xor_sync(0xffffffffu, s0, o);
        s1 += __shfl_xor_sync(0xffffffffu, s1, o);
        s2 += __shfl_xor_sync(0xffffffffu, s2, o);
        s3 += __shfl_xor_sync(0xffffffffu, s3, o);
        s4 += __shfl_xor_sync(0xffffffffu, s4, o);
        s5 += __shfl_xor_sync(0xffffffffu, s5, o);
        s6 += __shfl_xor_sync(0xffffffffu, s6, o);
        s7 += __shfl_xor_sync(0xffffffffu, s7, o);
    }

    if (lane < 8) {                      // lane j writes node base+j
        float lo = (lane & 2) ? ((lane & 1) ? s3 : s2) : ((lane & 1) ? s1 : s0);
        float hi = (lane & 2) ? ((lane & 1) ? s7 : s6) : ((lane & 1) ? s5 : s4);
        g_y0[base + lane] = (lane & 4) ? hi : lo;
    }
}

// Finalize per-node normalization after deg is complete.
__global__ void k_prep() {
    int i = blockIdx.x * blockDim.x + threadIdx.x;
    if (i >= NN) return;
    float deg = (float)(1 + g_degcnt[i]);   // +1 = self loop
    float y0  = g_y0[i];
    float dis = rsqrtf(deg);
    g_dis[i] = dis;
    g_z0[i]  = dis * y0;
    g_y1s[i] = y0 / deg;
}

// Edge scatter, 1 edge/thread, 3 mem ops: LDG.64 pair -> gather -> RED.
template <int PASS>
__global__ void __launch_bounds__(TB) k_pass() {
    int e = blockIdx.x * blockDim.x + threadIdx.x;
    if (e >= EE) return;
    int2 p = g_pairs[e];
    if (PASS == 1) atomicAdd(&g_t1[p.y], __ldg(&g_z0[p.x]));
    else           atomicAdd(&g_t2[p.y], __ldg(&g_z1[p.x]));
}

// z1 = dis * (dis*t1 + y0/deg)
__global__ void k_mid() {
    int i = blockIdx.x * blockDim.x + threadIdx.x;
    if (i >= NN) return;
    float dis = g_dis[i];
    g_z1[i] = dis * (dis * g_t1[i] + g_y1s[i]);
}

// out = dis*(t2 + z1) + b; then reset persistent state for the next call.
__global__ void k_final(float* __restrict__ out, const float* __restrict__ b) {
    int i = blockIdx.x * blockDim.x + threadIdx.x;
    if (i >= NN) return;
    out[i] = g_dis[i] * (g_t2[i] + g_z1[i]) + b[0];
    g_degcnt[i] = 0;
    g_t1[i] = 0.0f;
    g_t2[i] = 0.0f;
}

// ---------------------------------------------------------------------------
extern "C" void kernel_launch(void* const* d_in, const int* in_sizes, int n_in,
                              void* d_out, int out_size) {
    const float* x  = (const float*)d_in[0];
    const void*  ei = d_in[1];
    const float* W  = (const float*)d_in[2];
    const float* b  = (const float*)d_in[3];
    float* out = (float*)d_out;

    k_deg_dot<<<DOT_BLOCKS + EDGE_BLOCKS, TB>>>(ei, x, W);
    k_prep   <<<(NN + TB - 1) / TB, TB>>>();
    k_pass<1><<<EDGE_BLOCKS, TB>>>();
    k_mid    <<<(NN + TB - 1) / TB, TB>>>();
    k_pass<2><<<EDGE_BLOCKS, TB>>>();
    k_final  <<<(NN + TB - 1) / TB, TB>>>(out, b);
}